// round 10
// baseline (speedup 1.0000x reference)
#include <cuda_runtime.h>
#include <cstdint>

#define D_MODEL  1024
#define N_CTX    2049
#define B_SZ     2
#define SEQ_LEN  2048
#define M_ROWS   (B_SZ * N_CTX)   /* 4098 */
#define N_HEADS  16
#define D_K      64
#define N_LAYERS 16
#define VOCAB    256
#define QKV_N    3072

typedef unsigned long long ull;

// ---------------- device scratch ----------------
__device__ float g_X[M_ROWS * D_MODEL];
__device__ float g_QKV[M_ROWS * QKV_N];
__device__ float g_O[M_ROWS * D_MODEL];
__device__ float g_Wc[N_LAYERS * D_MODEL * QKV_N];   // concat [Wq|Wk|Wv] per layer

// ---------------- packed f32x2 helpers ----------------
__device__ __forceinline__ ull pack2(float x, float y) {
    ull r; asm("mov.b64 %0, {%1, %2};" : "=l"(r) : "f"(x), "f"(y)); return r;
}
__device__ __forceinline__ void fma2(ull& d, ull a, ull b) {
    asm("fma.rn.f32x2 %0, %1, %2, %3;" : "=l"(d) : "l"(a), "l"(b), "l"(d));
}
__device__ __forceinline__ ull mul2(ull a, ull b) {
    ull r; asm("mul.rn.f32x2 %0, %1, %2;" : "=l"(r) : "l"(a), "l"(b)); return r;
}
__device__ __forceinline__ float2 unpack2(ull v) {
    float2 r; asm("mov.b64 {%0, %1}, %2;" : "=f"(r.x), "=f"(r.y) : "l"(v)); return r;
}

// ---------------- embedding (with bos prepend) ----------------
__global__ void embed_kernel(const int* __restrict__ ids, const float* __restrict__ emb) {
    int i = blockIdx.x * blockDim.x + threadIdx.x;
    if (i >= M_ROWS * D_MODEL) return;
    int r = i >> 10;
    int d = i & 1023;
    int b = r / N_CTX;
    int t = r - b * N_CTX;
    int tok = (t == 0) ? 0 : ids[b * SEQ_LEN + (t - 1)];
    g_X[i] = emb[tok * D_MODEL + d];
}

// ---------------- concat Wq|Wk|Wv -> Wc[l][k][3072] ----------------
__global__ void wconcat_kernel(const float* __restrict__ Wq, const float* __restrict__ Wk,
                               const float* __restrict__ Wv) {
    int i = blockIdx.x * blockDim.x + threadIdx.x;
    if (i >= N_LAYERS * D_MODEL * QKV_N) return;
    int n = i % QKV_N;
    int rest = i / QKV_N;            // l*1024 + k
    size_t src = (size_t)rest * 1024 + (n & 1023);
    float v;
    if (n < 1024)      v = Wq[src];
    else if (n < 2048) v = Wk[src];
    else               v = Wv[src];
    g_Wc[i] = v;
}

// ---------------- SGEMM v3: 64x128 tile, 128 threads, A pre-duplicated pairs ----------------
__global__ __launch_bounds__(128, 4) void sgemm1024(const float* __restrict__ A,
                                                    const float* __restrict__ Bw, int ldb,
                                                    const float* __restrict__ Res,
                                                    float* __restrict__ C, int ldc) {
    __shared__ ull Asd[16][64];        // [k][m], each entry = (a,a) duplicated — 8KB
    __shared__ float Bs[16][128];      // 8KB
    const int tid = threadIdx.x;
    const int tx = tid & 15;           // col group: tx*8
    const int ty = tid >> 4;           // row group: ty*8 (0..7)
    const int row0 = blockIdx.y * 64;
    const int col0 = blockIdx.x * 128;

    ull c2[8][4];
    #pragma unroll
    for (int i = 0; i < 8; i++)
        #pragma unroll
        for (int j = 0; j < 4; j++) c2[i][j] = 0ULL;

    for (int k0 = 0; k0 < 1024; k0 += 16) {
        __syncthreads();
        // A tile (transposed + pair-duplicated): 64x16 = 256 float4, 2 per thread
        #pragma unroll
        for (int it = 0; it < 2; it++) {
            int idx = tid + it * 128;
            int m = idx >> 2;
            int kq = (idx & 3) << 2;
            int gr = row0 + m;
            float4 v = make_float4(0.f, 0.f, 0.f, 0.f);
            if (gr < M_ROWS) v = *(const float4*)&A[(size_t)gr * 1024 + k0 + kq];
            Asd[kq + 0][m] = pack2(v.x, v.x);
            Asd[kq + 1][m] = pack2(v.y, v.y);
            Asd[kq + 2][m] = pack2(v.z, v.z);
            Asd[kq + 3][m] = pack2(v.w, v.w);
        }
        // B tile: 16x128 = 512 float4, 4 per thread
        #pragma unroll
        for (int it = 0; it < 4; it++) {
            int idx = tid + it * 128;
            int k = idx >> 5;
            int nq = (idx & 31) << 2;
            *(float4*)&Bs[k][nq] = *(const float4*)&Bw[(size_t)(k0 + k) * ldb + col0 + nq];
        }
        __syncthreads();
        #pragma unroll
        for (int kk = 0; kk < 16; kk++) {
            const ull* ap = &Asd[kk][ty * 8];
            ulonglong2 a01 = *(const ulonglong2*)&ap[0];
            ulonglong2 a23 = *(const ulonglong2*)&ap[2];
            ulonglong2 a45 = *(const ulonglong2*)&ap[4];
            ulonglong2 a67 = *(const ulonglong2*)&ap[6];
            const ull* bu = (const ull*)&Bs[kk][tx * 8];
            ull b0 = bu[0], b1 = bu[1], b2v = bu[2], b3 = bu[3];
            ull ad[8] = {a01.x, a01.y, a23.x, a23.y, a45.x, a45.y, a67.x, a67.y};
            #pragma unroll
            for (int i = 0; i < 8; i++) {
                fma2(c2[i][0], ad[i], b0);
                fma2(c2[i][1], ad[i], b1);
                fma2(c2[i][2], ad[i], b2v);
                fma2(c2[i][3], ad[i], b3);
            }
        }
    }
    #pragma unroll
    for (int i = 0; i < 8; i++) {
        int gr = row0 + ty * 8 + i;
        if (gr >= M_ROWS) continue;
        #pragma unroll
        for (int j = 0; j < 4; j++) {
            float2 cc = unpack2(c2[i][j]);
            int col = col0 + tx * 8 + j * 2;
            if (Res) {
                float2 r = *(const float2*)&Res[(size_t)gr * 1024 + col];
                cc.x += r.x; cc.y += r.y;
            }
            *(float2*)&C[(size_t)gr * ldc + col] = cc;
        }
    }
}

// ---------------- tiled flash attention: 128q x 64k, reg-pipelined K/V ----------------
// Q/K/V packed in QKV[M][3072] at offsets h*64 / 1024+h*64 / 2048+h*64.
#define ATQ 128
#define ATK 64
#define QS_LD 132
#define KS_LD 68
#define VS_LD 68
#define PS_LD 132
#define ATTN_SMEM ((64 * QS_LD + 64 * KS_LD + ATK * VS_LD + ATK * PS_LD) * 4)

__global__ __launch_bounds__(256) void attn_kernel(const float* __restrict__ QKV,
                                                   float* __restrict__ Om) {
    extern __shared__ float sm[];
    float* Qs = sm;                        // [64 d][QS_LD q]
    float* Ks = Qs + 64 * QS_LD;           // [64 d][KS_LD k]
    float* Vs = Ks + 64 * KS_LD;           // [64 k][VS_LD d]
    float* Ps = Vs + ATK * VS_LD;          // [64 k][PS_LD q], q-cols XOR-swizzled

    const int h = blockIdx.y;
    const int b = blockIdx.z;
    int q0 = blockIdx.x * ATQ;
    if (q0 + ATQ > N_CTX) q0 = N_CTX - ATQ;     // overlap recomputes identical rows
    const int tid = threadIdx.x;
    const int tx = tid & 15;               // k group (tx*4) / d group (tx*4)
    const int ty = tid >> 4;               // q group (ty*8)
    const size_t brow = (size_t)b * N_CTX;
    const float* Qg = QKV + h * 64;
    const float* Kg = QKV + 1024 + h * 64;
    const float* Vg = QKV + 2048 + h * 64;

    // load Q tile transposed, pre-scaled by 1/8
    #pragma unroll
    for (int i = 0; i < 8; i++) {
        int idx = tid + i * 256;           // 0..2047
        int q = idx >> 4;
        int d4 = (idx & 15) << 2;
        float4 v = *(const float4*)(Qg + (brow + q0 + q) * QKV_N + d4);
        Qs[(d4 + 0) * QS_LD + q] = v.x * 0.125f;
        Qs[(d4 + 1) * QS_LD + q] = v.y * 0.125f;
        Qs[(d4 + 2) * QS_LD + q] = v.z * 0.125f;
        Qs[(d4 + 3) * QS_LD + q] = v.w * 0.125f;
    }

    ull o2[8][2];
    #pragma unroll
    for (int i = 0; i < 8; i++) { o2[i][0] = 0ULL; o2[i][1] = 0ULL; }
    float m[8], l[8];
    #pragma unroll
    for (int i = 0; i < 8; i++) { m[i] = -1e30f; l[i] = 0.f; }

    // K/V loader indices: 4 (k, float4-of-d) elements per thread per tile
    const int lk = tid >> 4;               // key 0..15 (+16/32/48)
    const int ld4 = (tid & 15) << 2;       // dim group

    const int ntiles = (q0 + ATQ + ATK - 1) / ATK;

    // prologue: load tile 0 K/V into regs
    float4 rk[4], rv[4];
    #pragma unroll
    for (int i = 0; i < 4; i++) {
        int kg = lk + 16 * i;              // tile 0: kg < 64 <= N_CTX always valid
        rk[i] = *(const float4*)(Kg + (brow + kg) * QKV_N + ld4);
        rv[i] = *(const float4*)(Vg + (brow + kg) * QKV_N + ld4);
    }

    for (int t = 0; t < ntiles; t++) {
        const int k0 = t * ATK;
        __syncthreads();                   // prev tile's Ks/Vs/Ps reads done; Qs visible (t=0)
        // store regs (tile t) into smem
        #pragma unroll
        for (int i = 0; i < 4; i++) {
            int k = lk + 16 * i;
            Ks[(ld4 + 0) * KS_LD + k] = rk[i].x;
            Ks[(ld4 + 1) * KS_LD + k] = rk[i].y;
            Ks[(ld4 + 2) * KS_LD + k] = rk[i].z;
            Ks[(ld4 + 3) * KS_LD + k] = rk[i].w;
            *(float4*)&Vs[k * VS_LD + ld4] = rv[i];
        }
        __syncthreads();
        // issue loads for tile t+1 (latency overlapped with compute below)
        if (t + 1 < ntiles) {
            #pragma unroll
            for (int i = 0; i < 4; i++) {
                int kg = k0 + ATK + lk + 16 * i;
                if (kg > N_CTX - 1) kg = N_CTX - 1;
                rk[i] = *(const float4*)(Kg + (brow + kg) * QKV_N + ld4);
                rv[i] = *(const float4*)(Vg + (brow + kg) * QKV_N + ld4);
            }
        }

        // ---- S = Q @ K^T (8q x 4k micro, FFMA2) ----
        ull c2[8][2];
        #pragma unroll
        for (int i = 0; i < 8; i++) { c2[i][0] = 0ULL; c2[i][1] = 0ULL; }
        #pragma unroll 4
        for (int d = 0; d < 64; d++) {
            float4 qa = *(const float4*)&Qs[d * QS_LD + ty * 8];
            float4 qb = *(const float4*)&Qs[d * QS_LD + ty * 8 + 4];
            ulonglong2 kk = *(const ulonglong2*)&Ks[d * KS_LD + tx * 4];
            float qv[8] = {qa.x, qa.y, qa.z, qa.w, qb.x, qb.y, qb.z, qb.w};
            #pragma unroll
            for (int i = 0; i < 8; i++) {
                ull qd = pack2(qv[i], qv[i]);
                fma2(c2[i][0], qd, kk.x);
                fma2(c2[i][1], qd, kk.y);
            }
        }

        // ---- softmax (online, per-row across 16 row-mates) ----
        float s[8][4];
        #pragma unroll
        for (int i = 0; i < 8; i++) {
            float2 u0 = unpack2(c2[i][0]);
            float2 u1 = unpack2(c2[i][1]);
            s[i][0] = u0.x; s[i][1] = u0.y; s[i][2] = u1.x; s[i][3] = u1.y;
        }
        if (k0 + ATK - 1 > q0) {           // tile touches/crosses diagonal -> mask
            #pragma unroll
            for (int i = 0; i < 8; i++) {
                int qg = q0 + ty * 8 + i;
                #pragma unroll
                for (int j = 0; j < 4; j++)
                    if (k0 + tx * 4 + j > qg) s[i][j] = -1e30f;
            }
        }
        #pragma unroll
        for (int i = 0; i < 8; i++) {
            float mt = fmaxf(fmaxf(s[i][0], s[i][1]), fmaxf(s[i][2], s[i][3]));
            mt = fmaxf(mt, __shfl_xor_sync(0xffffffffu, mt, 1));
            mt = fmaxf(mt, __shfl_xor_sync(0xffffffffu, mt, 2));
            mt = fmaxf(mt, __shfl_xor_sync(0xffffffffu, mt, 4));
            mt = fmaxf(mt, __shfl_xor_sync(0xffffffffu, mt, 8));
            float mn = fmaxf(m[i], mt);
            float corr = __expf(m[i] - mn);
            m[i] = mn;
            l[i] *= corr;
            ull cp = pack2(corr, corr);
            o2[i][0] = mul2(o2[i][0], cp);
            o2[i][1] = mul2(o2[i][1], cp);
            float rs = 0.f;
            #pragma unroll
            for (int j = 0; j < 4; j++) {
                float p = __expf(s[i][j] - mn);
                s[i][j] = p;
                rs += p;
            }
            l[i] += rs;
        }

        // ---- store P transposed: Ps[k][q] (swizzled float4 along q) ----
        {
            int swz = 4 * (tx & 7);
            #pragma unroll
            for (int j = 0; j < 4; j++) {
                float* prow = &Ps[(tx * 4 + j) * PS_LD];
                *(float4*)&prow[(ty * 8) ^ swz] =
                    make_float4(s[0][j], s[1][j], s[2][j], s[3][j]);
                *(float4*)&prow[(ty * 8 + 4) ^ swz] =
                    make_float4(s[4][j], s[5][j], s[6][j], s[7][j]);
            }
        }
        __syncthreads();

        // ---- O += P @ V (8q x 4d micro, FFMA2) ----
        #pragma unroll 4
        for (int k = 0; k < ATK; k++) {
            int swz = 4 * ((k >> 2) & 7);
            const float* prow = &Ps[k * PS_LD];
            float4 pa = *(const float4*)&prow[(ty * 8) ^ swz];
            float4 pb = *(const float4*)&prow[(ty * 8 + 4) ^ swz];
            ulonglong2 vv = *(const ulonglong2*)&Vs[k * VS_LD + tx * 4];
            float pv[8] = {pa.x, pa.y, pa.z, pa.w, pb.x, pb.y, pb.z, pb.w};
            #pragma unroll
            for (int i = 0; i < 8; i++) {
                ull pd = pack2(pv[i], pv[i]);
                fma2(o2[i][0], pd, vv.x);
                fma2(o2[i][1], pd, vv.y);
            }
        }
    }

    // ---- finalize: reduce l across row-mates, scale, write ----
    #pragma unroll
    for (int i = 0; i < 8; i++) {
        float lt = l[i];
        lt += __shfl_xor_sync(0xffffffffu, lt, 1);
        lt += __shfl_xor_sync(0xffffffffu, lt, 2);
        lt += __shfl_xor_sync(0xffffffffu, lt, 4);
        lt += __shfl_xor_sync(0xffffffffu, lt, 8);
        float inv = 1.f / lt;
        ull ip = pack2(inv, inv);
        float2 d01 = unpack2(mul2(o2[i][0], ip));
        float2 d23 = unpack2(mul2(o2[i][1], ip));
        float4 w = make_float4(d01.x, d01.y, d23.x, d23.y);
        *(float4*)(Om + (brow + q0 + ty * 8 + i) * D_MODEL + h * 64 + tx * 4) = w;
    }
}

// ---------------- fused logits + softmax into d_out slice l (f32x2 GEMV) ----------------
__global__ __launch_bounds__(256) void probs_kernel(const float* __restrict__ X,
                                                    const float* __restrict__ Wout,
                                                    float* __restrict__ out,
                                                    int l) {
    // rows stored pair-interleaved: xs2[p][k] = (X[row0+2p][k], X[row0+2p+1][k])
    __shared__ ull xs2[4][1024];            // 32 KB
    __shared__ float red[8][8];
    const int tid = threadIdx.x;
    const int row0 = blockIdx.x * 8;

    #pragma unroll
    for (int it = 0; it < 8; it++) {
        int idx = tid + it * 256;           // 0..2047 float4 loads
        int m = idx >> 8;                   // 0..7
        int c4 = idx & 255;
        int gr = row0 + m;
        float4 v = make_float4(0.f, 0.f, 0.f, 0.f);
        if (gr < M_ROWS) v = ((const float4*)&X[(size_t)gr * 1024])[c4];
        float* dst = (float*)&xs2[m >> 1][0];
        int e = m & 1;
        dst[(c4 * 4 + 0) * 2 + e] = v.x;
        dst[(c4 * 4 + 1) * 2 + e] = v.y;
        dst[(c4 * 4 + 2) * 2 + e] = v.z;
        dst[(c4 * 4 + 3) * 2 + e] = v.w;
    }
    __syncthreads();

    ull acce[4], acco[4];
    #pragma unroll
    for (int p = 0; p < 4; p++) { acce[p] = 0ULL; acco[p] = 0ULL; }
    const int v = tid;
    #pragma unroll 2
    for (int k = 0; k < 1024; k += 2) {
        float w0 = Wout[k * VOCAB + v];
        float w1 = Wout[(k + 1) * VOCAB + v];
        ull wp0 = pack2(w0, w0);
        ull wp1 = pack2(w1, w1);
        #pragma unroll
        for (int p = 0; p < 4; p++) {
            ulonglong2 x = *(const ulonglong2*)&xs2[p][k];
            fma2(acce[p], x.x, wp0);
            fma2(acco[p], x.y, wp1);
        }
    }
    float acc[8];
    #pragma unroll
    for (int p = 0; p < 4; p++) {
        float2 e = unpack2(acce[p]);
        float2 o = unpack2(acco[p]);
        acc[2 * p] = e.x + o.x;
        acc[2 * p + 1] = e.y + o.y;
    }

    const int lane = tid & 31;
    const int wid  = tid >> 5;
    float bmax[8];
    #pragma unroll
    for (int m = 0; m < 8; m++) {
        float x = acc[m];
        #pragma unroll
        for (int off = 16; off; off >>= 1)
            x = fmaxf(x, __shfl_xor_sync(0xffffffffu, x, off));
        if (lane == 0) red[m][wid] = x;
    }
    __syncthreads();
    #pragma unroll
    for (int m = 0; m < 8; m++) {
        float mx = red[m][0];
        #pragma unroll
        for (int w = 1; w < 8; w++) mx = fmaxf(mx, red[m][w]);
        bmax[m] = mx;
    }
    __syncthreads();
    float p[8];
    #pragma unroll
    for (int m = 0; m < 8; m++) {
        p[m] = __expf(acc[m] - bmax[m]);
        float x = p[m];
        #pragma unroll
        for (int off = 16; off; off >>= 1)
            x += __shfl_xor_sync(0xffffffffu, x, off);
        if (lane == 0) red[m][wid] = x;
    }
    __syncthreads();
    #pragma unroll
    for (int m = 0; m < 8; m++) {
        float sm = 0.f;
        #pragma unroll
        for (int w = 0; w < 8; w++) sm += red[m][w];
        int gr = row0 + m;
        if (gr < M_ROWS) {
            int b = gr / N_CTX;
            int t = gr - b * N_CTX;
            out[(((size_t)l * B_SZ + b) * N_CTX + t) * VOCAB + v] = p[m] / sm;
        }
    }
}

// ---------------- orchestration ----------------
extern "C" void kernel_launch(void* const* d_in, const int* in_sizes, int n_in,
                              void* d_out, int out_size) {
    const int*   ids  = (const int*)d_in[0];
    const float* emb  = (const float*)d_in[1];
    const float* Wq   = (const float*)d_in[2];
    const float* Wk   = (const float*)d_in[3];
    const float* Wv   = (const float*)d_in[4];
    const float* Wo   = (const float*)d_in[5];
    const float* Wout = (const float*)d_in[6];
    float* out = (float*)d_out;

    float *X, *QKV, *O, *Wc;
    cudaGetSymbolAddress((void**)&X, g_X);
    cudaGetSymbolAddress((void**)&QKV, g_QKV);
    cudaGetSymbolAddress((void**)&O, g_O);
    cudaGetSymbolAddress((void**)&Wc, g_Wc);

    cudaFuncSetAttribute(attn_kernel, cudaFuncAttributeMaxDynamicSharedMemorySize, ATTN_SMEM);

    wconcat_kernel<<<(N_LAYERS * D_MODEL * QKV_N + 255) / 256, 256>>>(Wq, Wk, Wv);
    embed_kernel<<<(M_ROWS * D_MODEL + 255) / 256, 256>>>(ids, emb);
    probs_kernel<<<(M_ROWS + 7) / 8, 256>>>(X, Wout, out, 0);

    dim3 qkvgrid(QKV_N / 128, (M_ROWS + 63) / 64);
    dim3 ogrid(D_MODEL / 128, (M_ROWS + 63) / 64);
    dim3 agrid((N_CTX + ATQ - 1) / ATQ, N_HEADS, B_SZ);
    for (int l = 0; l < N_LAYERS; l++) {
        const float* wc = Wc + (size_t)l * D_MODEL * QKV_N;
        const float* wo = Wo + (size_t)l * D_MODEL * D_MODEL;
        sgemm1024<<<qkvgrid, 128>>>(X, wc, QKV_N, nullptr, QKV, QKV_N);
        attn_kernel<<<agrid, 256, ATTN_SMEM>>>(QKV, O);
        sgemm1024<<<ogrid, 128>>>(O, wo, D_MODEL, X, X, D_MODEL);   // X += O @ Wo
        probs_kernel<<<(M_ROWS + 7) / 8, 256>>>(X, Wout, out, l + 1);
    }
}

// round 11
// speedup vs baseline: 1.7689x; 1.7689x over previous
#include <cuda_runtime.h>
#include <cstdint>

#define D_MODEL  1024
#define N_CTX    2049
#define B_SZ     2
#define SEQ_LEN  2048
#define M_ROWS   (B_SZ * N_CTX)   /* 4098 */
#define N_HEADS  16
#define D_K      64
#define N_LAYERS 16
#define VOCAB    256
#define QKV_N    3072

typedef unsigned long long ull;

// ---------------- device scratch ----------------
__device__ float g_X[M_ROWS * D_MODEL];
__device__ float g_QKV[M_ROWS * QKV_N];
__device__ float g_O[M_ROWS * D_MODEL];
__device__ float g_Wc[N_LAYERS * D_MODEL * QKV_N];   // concat [Wq|Wk|Wv] per layer

// ---------------- packed f32x2 helpers ----------------
__device__ __forceinline__ ull pack2(float x, float y) {
    ull r; asm("mov.b64 %0, {%1, %2};" : "=l"(r) : "f"(x), "f"(y)); return r;
}
__device__ __forceinline__ void fma2(ull& d, ull a, ull b) {
    asm("fma.rn.f32x2 %0, %1, %2, %3;" : "=l"(d) : "l"(a), "l"(b), "l"(d));
}
__device__ __forceinline__ ull mul2(ull a, ull b) {
    ull r; asm("mul.rn.f32x2 %0, %1, %2;" : "=l"(r) : "l"(a), "l"(b)); return r;
}
__device__ __forceinline__ float2 unpack2(ull v) {
    float2 r; asm("mov.b64 {%0, %1}, %2;" : "=f"(r.x), "=f"(r.y) : "l"(v)); return r;
}

// ---------------- embedding (with bos prepend) ----------------
__global__ void embed_kernel(const int* __restrict__ ids, const float* __restrict__ emb) {
    int i = blockIdx.x * blockDim.x + threadIdx.x;
    if (i >= M_ROWS * D_MODEL) return;
    int r = i >> 10;
    int d = i & 1023;
    int b = r / N_CTX;
    int t = r - b * N_CTX;
    int tok = (t == 0) ? 0 : ids[b * SEQ_LEN + (t - 1)];
    g_X[i] = emb[tok * D_MODEL + d];
}

// ---------------- concat Wq|Wk|Wv -> Wc[l][k][3072] ----------------
__global__ void wconcat_kernel(const float* __restrict__ Wq, const float* __restrict__ Wk,
                               const float* __restrict__ Wv) {
    int i = blockIdx.x * blockDim.x + threadIdx.x;
    if (i >= N_LAYERS * D_MODEL * QKV_N) return;
    int n = i % QKV_N;
    int rest = i / QKV_N;            // l*1024 + k
    size_t src = (size_t)rest * 1024 + (n & 1023);
    float v;
    if (n < 1024)      v = Wq[src];
    else if (n < 2048) v = Wk[src];
    else               v = Wv[src];
    g_Wc[i] = v;
}

// ---------------- SGEMM (R9-measured: 64x128 tile, 128 threads, 8x8 FFMA2 micro) --------
__global__ __launch_bounds__(128) void sgemm1024(const float* __restrict__ A,
                                                 const float* __restrict__ Bw, int ldb,
                                                 const float* __restrict__ Res,
                                                 float* __restrict__ C, int ldc) {
    __shared__ float As[16][64];
    __shared__ float Bs[16][128];
    const int tid = threadIdx.x;
    const int tx = tid & 15;           // col group: tx*8
    const int ty = tid >> 4;           // row group: ty*8 (0..7)
    const int row0 = blockIdx.y * 64;
    const int col0 = blockIdx.x * 128;

    ull c2[8][4];
    #pragma unroll
    for (int i = 0; i < 8; i++)
        #pragma unroll
        for (int j = 0; j < 4; j++) c2[i][j] = 0ULL;

    for (int k0 = 0; k0 < 1024; k0 += 16) {
        __syncthreads();
        // A tile (transposed): 64x16 = 256 float4, 2 per thread
        #pragma unroll
        for (int it = 0; it < 2; it++) {
            int idx = tid + it * 128;
            int m = idx >> 2;
            int kq = (idx & 3) << 2;
            int gr = row0 + m;
            float4 v = make_float4(0.f, 0.f, 0.f, 0.f);
            if (gr < M_ROWS) v = *(const float4*)&A[(size_t)gr * 1024 + k0 + kq];
            As[kq + 0][m] = v.x; As[kq + 1][m] = v.y;
            As[kq + 2][m] = v.z; As[kq + 3][m] = v.w;
        }
        // B tile: 16x128 = 512 float4, 4 per thread
        #pragma unroll
        for (int it = 0; it < 4; it++) {
            int idx = tid + it * 128;
            int k = idx >> 5;
            int nq = (idx & 31) << 2;
            *(float4*)&Bs[k][nq] = *(const float4*)&Bw[(size_t)(k0 + k) * ldb + col0 + nq];
        }
        __syncthreads();
        #pragma unroll
        for (int kk = 0; kk < 16; kk++) {
            float4 a0 = *(const float4*)&As[kk][ty * 8];
            float4 a1 = *(const float4*)&As[kk][ty * 8 + 4];
            const ull* bu = (const ull*)&Bs[kk][tx * 8];
            ull b0 = bu[0], b1 = bu[1], b2v = bu[2], b3 = bu[3];
            float av[8] = {a0.x, a0.y, a0.z, a0.w, a1.x, a1.y, a1.z, a1.w};
            #pragma unroll
            for (int i = 0; i < 8; i++) {
                ull ad = pack2(av[i], av[i]);
                fma2(c2[i][0], ad, b0);
                fma2(c2[i][1], ad, b1);
                fma2(c2[i][2], ad, b2v);
                fma2(c2[i][3], ad, b3);
            }
        }
    }
    #pragma unroll
    for (int i = 0; i < 8; i++) {
        int gr = row0 + ty * 8 + i;
        if (gr >= M_ROWS) continue;
        #pragma unroll
        for (int j = 0; j < 4; j++) {
            float2 cc = unpack2(c2[i][j]);
            int col = col0 + tx * 8 + j * 2;
            if (Res) {
                float2 r = *(const float2*)&Res[(size_t)gr * 1024 + col];
                cc.x += r.x; cc.y += r.y;
            }
            *(float2*)&C[(size_t)gr * ldc + col] = cc;
        }
    }
}

// ---------------- tiled flash attention (R8-measured: 128q x 128k tiles) ----------------
// Q/K/V packed in QKV[M][3072] at offsets h*64 / 1024+h*64 / 2048+h*64.
#define ATQ 128
#define ATK 128
#define QS_LD 132
#define VS_LD 68
#define PS_LD 132
#define ATTN_SMEM ((64 * QS_LD + 64 * QS_LD + ATK * VS_LD + ATK * PS_LD) * 4)

__global__ __launch_bounds__(256) void attn_kernel(const float* __restrict__ QKV,
                                                   float* __restrict__ Om) {
    extern __shared__ float sm[];
    float* Qs = sm;                        // [64][QS_LD]  d-major
    float* Ks = Qs + 64 * QS_LD;           // [64][QS_LD]  d-major
    float* Vs = Ks + 64 * QS_LD;           // [128][VS_LD] k-major
    float* Ps = Vs + ATK * VS_LD;          // [128][PS_LD] k-major, q-cols XOR-swizzled

    const int h = blockIdx.y;
    const int b = blockIdx.z;
    int q0 = blockIdx.x * ATQ;
    if (q0 + ATQ > N_CTX) q0 = N_CTX - ATQ;     // overlap recomputes identical rows
    const int tid = threadIdx.x;
    const int tx = tid & 15;
    const int ty = tid >> 4;
    const size_t brow = (size_t)b * N_CTX;
    const float* Qg = QKV + h * 64;
    const float* Kg = QKV + 1024 + h * 64;
    const float* Vg = QKV + 2048 + h * 64;

    // load Q tile transposed, pre-scaled by 1/8
    #pragma unroll
    for (int i = 0; i < 8; i++) {
        int idx = tid + i * 256;           // 0..2047
        int q = idx >> 4;
        int d4 = (idx & 15) << 2;
        float4 v = *(const float4*)(Qg + (brow + q0 + q) * QKV_N + d4);
        Qs[(d4 + 0) * QS_LD + q] = v.x * 0.125f;
        Qs[(d4 + 1) * QS_LD + q] = v.y * 0.125f;
        Qs[(d4 + 2) * QS_LD + q] = v.z * 0.125f;
        Qs[(d4 + 3) * QS_LD + q] = v.w * 0.125f;
    }

    ull o2[8][2];
    #pragma unroll
    for (int i = 0; i < 8; i++) { o2[i][0] = 0ULL; o2[i][1] = 0ULL; }
    float m[8], l[8];
    #pragma unroll
    for (int i = 0; i < 8; i++) { m[i] = -1e30f; l[i] = 0.f; }

    const int ntiles = (q0 + ATQ + ATK - 1) / ATK;
    for (int t = 0; t < ntiles; t++) {
        const int k0 = t * ATK;
        __syncthreads();                   // Ks/Vs free (prev tile done), Qs visible (t=0)
        // load K (transposed) and V for this k-tile
        #pragma unroll
        for (int i = 0; i < 8; i++) {
            int idx = tid + i * 256;
            int k = idx >> 4;
            int d4 = (idx & 15) << 2;
            int kg = k0 + k; if (kg > N_CTX - 1) kg = N_CTX - 1;
            float4 kv = *(const float4*)(Kg + (brow + kg) * QKV_N + d4);
            Ks[(d4 + 0) * QS_LD + k] = kv.x;
            Ks[(d4 + 1) * QS_LD + k] = kv.y;
            Ks[(d4 + 2) * QS_LD + k] = kv.z;
            Ks[(d4 + 3) * QS_LD + k] = kv.w;
            float4 vv = *(const float4*)(Vg + (brow + kg) * QKV_N + d4);
            *(float4*)&Vs[k * VS_LD + d4] = vv;
        }
        __syncthreads();

        // ---- S = Q @ K^T (8x8 micro, FFMA2) ----
        ull c2[8][4];
        #pragma unroll
        for (int i = 0; i < 8; i++)
            #pragma unroll
            for (int j = 0; j < 4; j++) c2[i][j] = 0ULL;
        #pragma unroll 2
        for (int d = 0; d < 64; d++) {
            float4 qa = *(const float4*)&Qs[d * QS_LD + ty * 8];
            float4 qb = *(const float4*)&Qs[d * QS_LD + ty * 8 + 4];
            ulonglong2 k01 = *(const ulonglong2*)&Ks[d * QS_LD + tx * 8];
            ulonglong2 k23 = *(const ulonglong2*)&Ks[d * QS_LD + tx * 8 + 4];
            float qv[8] = {qa.x, qa.y, qa.z, qa.w, qb.x, qb.y, qb.z, qb.w};
            #pragma unroll
            for (int i = 0; i < 8; i++) {
                ull qd = pack2(qv[i], qv[i]);
                fma2(c2[i][0], qd, k01.x);
                fma2(c2[i][1], qd, k01.y);
                fma2(c2[i][2], qd, k23.x);
                fma2(c2[i][3], qd, k23.y);
            }
        }

        // ---- softmax (online, per-row across 16 row-mates) ----
        float s[8][8];
        #pragma unroll
        for (int i = 0; i < 8; i++)
            #pragma unroll
            for (int jp = 0; jp < 4; jp++) {
                float2 u = unpack2(c2[i][jp]);
                s[i][2 * jp] = u.x; s[i][2 * jp + 1] = u.y;
            }
        if (k0 + ATK - 1 > q0) {           // tile touches/crosses diagonal -> mask
            #pragma unroll
            for (int i = 0; i < 8; i++) {
                int qg = q0 + ty * 8 + i;
                #pragma unroll
                for (int j = 0; j < 8; j++)
                    if (k0 + tx * 8 + j > qg) s[i][j] = -1e30f;
            }
        }
        #pragma unroll
        for (int i = 0; i < 8; i++) {
            float mt = s[i][0];
            #pragma unroll
            for (int j = 1; j < 8; j++) mt = fmaxf(mt, s[i][j]);
            mt = fmaxf(mt, __shfl_xor_sync(0xffffffffu, mt, 1));
            mt = fmaxf(mt, __shfl_xor_sync(0xffffffffu, mt, 2));
            mt = fmaxf(mt, __shfl_xor_sync(0xffffffffu, mt, 4));
            mt = fmaxf(mt, __shfl_xor_sync(0xffffffffu, mt, 8));
            float mn = fmaxf(m[i], mt);
            float corr = __expf(m[i] - mn);
            m[i] = mn;
            l[i] *= corr;
            ull cp = pack2(corr, corr);
            o2[i][0] = mul2(o2[i][0], cp);
            o2[i][1] = mul2(o2[i][1], cp);
            float rs = 0.f;
            #pragma unroll
            for (int j = 0; j < 8; j++) {
                float p = __expf(s[i][j] - mn);
                s[i][j] = p;
                rs += p;
            }
            l[i] += rs;
        }

        // ---- store P transposed: Ps[k][q] (swizzled float4 along q) ----
        {
            int swz = 4 * (tx & 7);
            #pragma unroll
            for (int j = 0; j < 8; j++) {
                float* prow = &Ps[(tx * 8 + j) * PS_LD];
                *(float4*)&prow[(ty * 8) ^ swz] =
                    make_float4(s[0][j], s[1][j], s[2][j], s[3][j]);
                *(float4*)&prow[(ty * 8 + 4) ^ swz] =
                    make_float4(s[4][j], s[5][j], s[6][j], s[7][j]);
            }
        }
        __syncthreads();

        // ---- O += P @ V (8q x 4d micro, FFMA2) ----
        #pragma unroll 2
        for (int k = 0; k < ATK; k++) {
            int swz = 4 * ((k >> 3) & 7);
            const float* prow = &Ps[k * PS_LD];
            float4 pa = *(const float4*)&prow[(ty * 8) ^ swz];
            float4 pb = *(const float4*)&prow[(ty * 8 + 4) ^ swz];
            ulonglong2 vv = *(const ulonglong2*)&Vs[k * VS_LD + tx * 4];
            float pv[8] = {pa.x, pa.y, pa.z, pa.w, pb.x, pb.y, pb.z, pb.w};
            #pragma unroll
            for (int i = 0; i < 8; i++) {
                ull pd = pack2(pv[i], pv[i]);
                fma2(o2[i][0], pd, vv.x);
                fma2(o2[i][1], pd, vv.y);
            }
        }
    }

    // ---- finalize: reduce l across row-mates, scale, write ----
    #pragma unroll
    for (int i = 0; i < 8; i++) {
        float lt = l[i];
        lt += __shfl_xor_sync(0xffffffffu, lt, 1);
        lt += __shfl_xor_sync(0xffffffffu, lt, 2);
        lt += __shfl_xor_sync(0xffffffffu, lt, 4);
        lt += __shfl_xor_sync(0xffffffffu, lt, 8);
        float inv = 1.f / lt;
        ull ip = pack2(inv, inv);
        float2 d01 = unpack2(mul2(o2[i][0], ip));
        float2 d23 = unpack2(mul2(o2[i][1], ip));
        float4 w = make_float4(d01.x, d01.y, d23.x, d23.y);
        *(float4*)(Om + (brow + q0 + ty * 8 + i) * D_MODEL + h * 64 + tx * 4) = w;
    }
}

// ---------------- fused logits + softmax into d_out slice l (f32x2 GEMV) ----------------
__global__ __launch_bounds__(256) void probs_kernel(const float* __restrict__ X,
                                                    const float* __restrict__ Wout,
                                                    float* __restrict__ out,
                                                    int l) {
    // rows stored pair-interleaved: xs2[p][k] = (X[row0+2p][k], X[row0+2p+1][k])
    __shared__ ull xs2[4][1024];            // 32 KB
    __shared__ float red[8][8];
    const int tid = threadIdx.x;
    const int row0 = blockIdx.x * 8;

    #pragma unroll
    for (int it = 0; it < 8; it++) {
        int idx = tid + it * 256;           // 0..2047 float4 loads
        int m = idx >> 8;                   // 0..7
        int c4 = idx & 255;
        int gr = row0 + m;
        float4 v = make_float4(0.f, 0.f, 0.f, 0.f);
        if (gr < M_ROWS) v = ((const float4*)&X[(size_t)gr * 1024])[c4];
        float* dst = (float*)&xs2[m >> 1][0];
        int e = m & 1;
        dst[(c4 * 4 + 0) * 2 + e] = v.x;
        dst[(c4 * 4 + 1) * 2 + e] = v.y;
        dst[(c4 * 4 + 2) * 2 + e] = v.z;
        dst[(c4 * 4 + 3) * 2 + e] = v.w;
    }
    __syncthreads();

    ull acce[4], acco[4];
    #pragma unroll
    for (int p = 0; p < 4; p++) { acce[p] = 0ULL; acco[p] = 0ULL; }
    const int v = tid;
    #pragma unroll 2
    for (int k = 0; k < 1024; k += 2) {
        float w0 = Wout[k * VOCAB + v];
        float w1 = Wout[(k + 1) * VOCAB + v];
        ull wp0 = pack2(w0, w0);
        ull wp1 = pack2(w1, w1);
        #pragma unroll
        for (int p = 0; p < 4; p++) {
            ulonglong2 x = *(const ulonglong2*)&xs2[p][k];
            fma2(acce[p], x.x, wp0);
            fma2(acco[p], x.y, wp1);
        }
    }
    float acc[8];
    #pragma unroll
    for (int p = 0; p < 4; p++) {
        float2 e = unpack2(acce[p]);
        float2 o = unpack2(acco[p]);
        acc[2 * p] = e.x + o.x;
        acc[2 * p + 1] = e.y + o.y;
    }

    const int lane = tid & 31;
    const int wid  = tid >> 5;
    float bmax[8];
    #pragma unroll
    for (int m = 0; m < 8; m++) {
        float x = acc[m];
        #pragma unroll
        for (int off = 16; off; off >>= 1)
            x = fmaxf(x, __shfl_xor_sync(0xffffffffu, x, off));
        if (lane == 0) red[m][wid] = x;
    }
    __syncthreads();
    #pragma unroll
    for (int m = 0; m < 8; m++) {
        float mx = red[m][0];
        #pragma unroll
        for (int w = 1; w < 8; w++) mx = fmaxf(mx, red[m][w]);
        bmax[m] = mx;
    }
    __syncthreads();
    float p[8];
    #pragma unroll
    for (int m = 0; m < 8; m++) {
        p[m] = __expf(acc[m] - bmax[m]);
        float x = p[m];
        #pragma unroll
        for (int off = 16; off; off >>= 1)
            x += __shfl_xor_sync(0xffffffffu, x, off);
        if (lane == 0) red[m][wid] = x;
    }
    __syncthreads();
    #pragma unroll
    for (int m = 0; m < 8; m++) {
        float sm = 0.f;
        #pragma unroll
        for (int w = 0; w < 8; w++) sm += red[m][w];
        int gr = row0 + m;
        if (gr < M_ROWS) {
            int b = gr / N_CTX;
            int t = gr - b * N_CTX;
            out[(((size_t)l * B_SZ + b) * N_CTX + t) * VOCAB + v] = p[m] / sm;
        }
    }
}

// ---------------- orchestration ----------------
extern "C" void kernel_launch(void* const* d_in, const int* in_sizes, int n_in,
                              void* d_out, int out_size) {
    const int*   ids  = (const int*)d_in[0];
    const float* emb  = (const float*)d_in[1];
    const float* Wq   = (const float*)d_in[2];
    const float* Wk   = (const float*)d_in[3];
    const float* Wv   = (const float*)d_in[4];
    const float* Wo   = (const float*)d_in[5];
    const float* Wout = (const float*)d_in[6];
    float* out = (float*)d_out;

    float *X, *QKV, *O, *Wc;
    cudaGetSymbolAddress((void**)&X, g_X);
    cudaGetSymbolAddress((void**)&QKV, g_QKV);
    cudaGetSymbolAddress((void**)&O, g_O);
    cudaGetSymbolAddress((void**)&Wc, g_Wc);

    cudaFuncSetAttribute(attn_kernel, cudaFuncAttributeMaxDynamicSharedMemorySize, ATTN_SMEM);

    wconcat_kernel<<<(N_LAYERS * D_MODEL * QKV_N + 255) / 256, 256>>>(Wq, Wk, Wv);
    embed_kernel<<<(M_ROWS * D_MODEL + 255) / 256, 256>>>(ids, emb);
    probs_kernel<<<(M_ROWS + 7) / 8, 256>>>(X, Wout, out, 0);

    dim3 qkvgrid(QKV_N / 128, (M_ROWS + 63) / 64);
    dim3 ogrid(D_MODEL / 128, (M_ROWS + 63) / 64);
    dim3 agrid((N_CTX + ATQ - 1) / ATQ, N_HEADS, B_SZ);
    for (int l = 0; l < N_LAYERS; l++) {
        const float* wc = Wc + (size_t)l * D_MODEL * QKV_N;
        const float* wo = Wo + (size_t)l * D_MODEL * D_MODEL;
        sgemm1024<<<qkvgrid, 128>>>(X, wc, QKV_N, nullptr, QKV, QKV_N);
        attn_kernel<<<agrid, 256, ATTN_SMEM>>>(QKV, O);
        sgemm1024<<<ogrid, 128>>>(O, wo, D_MODEL, X, X, D_MODEL);   // X += O @ Wo
        probs_kernel<<<(M_ROWS + 7) / 8, 256>>>(X, Wout, out, l + 1);
    }
}

// round 13
// speedup vs baseline: 1.8464x; 1.0438x over previous
#include <cuda_runtime.h>
#include <cstdint>

#define D_MODEL  1024
#define N_CTX    2049
#define B_SZ     2
#define SEQ_LEN  2048
#define M_ROWS   (B_SZ * N_CTX)   /* 4098 */
#define N_HEADS  16
#define D_K      64
#define N_LAYERS 16
#define VOCAB    256
#define QKV_N    3072

typedef unsigned long long ull;

// ---------------- device scratch ----------------
__device__ float g_X[M_ROWS * D_MODEL];
__device__ float g_QKV[M_ROWS * QKV_N];
__device__ float g_O[M_ROWS * D_MODEL];
__device__ float g_Wc[N_LAYERS * D_MODEL * QKV_N];   // concat [Wq|Wk|Wv] per layer

// ---------------- packed f32x2 helpers ----------------
__device__ __forceinline__ ull pack2(float x, float y) {
    ull r; asm("mov.b64 %0, {%1, %2};" : "=l"(r) : "f"(x), "f"(y)); return r;
}
__device__ __forceinline__ void fma2(ull& d, ull a, ull b) {
    asm("fma.rn.f32x2 %0, %1, %2, %3;" : "=l"(d) : "l"(a), "l"(b), "l"(d));
}
__device__ __forceinline__ ull mul2(ull a, ull b) {
    ull r; asm("mul.rn.f32x2 %0, %1, %2;" : "=l"(r) : "l"(a), "l"(b)); return r;
}
__device__ __forceinline__ float2 unpack2(ull v) {
    float2 r; asm("mov.b64 {%0, %1}, %2;" : "=f"(r.x), "=f"(r.y) : "l"(v)); return r;
}

// ---------------- cp.async helpers (sm_80+ family-common) ----------------
__device__ __forceinline__ uint32_t smem_u32(const void* p) {
    uint32_t a;
    asm("{ .reg .u64 t; cvta.to.shared.u64 t, %1; cvt.u32.u64 %0, t; }" : "=r"(a) : "l"(p));
    return a;
}
__device__ __forceinline__ void cp16(uint32_t dst, const void* src) {
    asm volatile("cp.async.cg.shared.global [%0], [%1], 16;" :: "r"(dst), "l"(src) : "memory");
}
#define CP_COMMIT() asm volatile("cp.async.commit_group;" ::: "memory")
#define CP_WAIT0()  asm volatile("cp.async.wait_group 0;" ::: "memory")

// ---------------- embedding (with bos prepend) ----------------
__global__ void embed_kernel(const int* __restrict__ ids, const float* __restrict__ emb) {
    int i = blockIdx.x * blockDim.x + threadIdx.x;
    if (i >= M_ROWS * D_MODEL) return;
    int r = i >> 10;
    int d = i & 1023;
    int b = r / N_CTX;
    int t = r - b * N_CTX;
    int tok = (t == 0) ? 0 : ids[b * SEQ_LEN + (t - 1)];
    g_X[i] = emb[tok * D_MODEL + d];
}

// ---------------- concat Wq|Wk|Wv -> Wc[l][k][3072] ----------------
__global__ void wconcat_kernel(const float* __restrict__ Wq, const float* __restrict__ Wk,
                               const float* __restrict__ Wv) {
    int i = blockIdx.x * blockDim.x + threadIdx.x;
    if (i >= N_LAYERS * D_MODEL * QKV_N) return;
    int n = i % QKV_N;
    int rest = i / QKV_N;            // l*1024 + k
    size_t src = (size_t)rest * 1024 + (n & 1023);
    float v;
    if (n < 1024)      v = Wq[src];
    else if (n < 2048) v = Wk[src];
    else               v = Wv[src];
    g_Wc[i] = v;
}

// ---------------- SGEMM v4: 64x128 tile, cp.async double-buffered ----------------
__global__ __launch_bounds__(128, 4) void sgemm1024(const float* __restrict__ A,
                                                    const float* __restrict__ Bw, int ldb,
                                                    const float* __restrict__ Res,
                                                    float* __restrict__ C, int ldc) {
    __shared__ float As[2][16][64];    // 8 KB
    __shared__ float Bs[2][16][128];   // 16 KB
    const int tid = threadIdx.x;
    const int tx = tid & 15;           // col group: tx*8
    const int ty = tid >> 4;           // row group: ty*8 (0..7)
    const int row0 = blockIdx.y * 64;
    const int col0 = blockIdx.x * 128;

    // loader indices
    const int aM0 = tid >> 2,           aK0 = (tid & 3) << 2;
    const int aM1 = (tid + 128) >> 2,   aK1 = ((tid + 128) & 3) << 2;
    const int agr0 = row0 + aM0, agr1 = row0 + aM1;
    const int bK = tid >> 5;            // +4 per iter
    const int bN = (tid & 31) << 2;

    ull c2[8][4];
    #pragma unroll
    for (int i = 0; i < 8; i++)
        #pragma unroll
        for (int j = 0; j < 4; j++) c2[i][j] = 0ULL;

    float4 ra0, ra1;
    // prologue: tile 0
    {
        ra0 = make_float4(0.f, 0.f, 0.f, 0.f);
        ra1 = make_float4(0.f, 0.f, 0.f, 0.f);
        if (agr0 < M_ROWS) ra0 = *(const float4*)&A[(size_t)agr0 * 1024 + aK0];
        if (agr1 < M_ROWS) ra1 = *(const float4*)&A[(size_t)agr1 * 1024 + aK1];
        As[0][aK0 + 0][aM0] = ra0.x; As[0][aK0 + 1][aM0] = ra0.y;
        As[0][aK0 + 2][aM0] = ra0.z; As[0][aK0 + 3][aM0] = ra0.w;
        As[0][aK1 + 0][aM1] = ra1.x; As[0][aK1 + 1][aM1] = ra1.y;
        As[0][aK1 + 2][aM1] = ra1.z; As[0][aK1 + 3][aM1] = ra1.w;
        #pragma unroll
        for (int it = 0; it < 4; it++) {
            int k = bK + it * 4;
            cp16(smem_u32(&Bs[0][k][bN]), &Bw[(size_t)k * ldb + col0 + bN]);
        }
        CP_COMMIT();
        CP_WAIT0();
        __syncthreads();
    }

    for (int kt = 0; kt < 64; kt++) {
        const int cur = kt & 1;
        const int nxt = cur ^ 1;
        if (kt < 63) {
            const int k0n = (kt + 1) * 16;
            ra0 = make_float4(0.f, 0.f, 0.f, 0.f);
            ra1 = make_float4(0.f, 0.f, 0.f, 0.f);
            if (agr0 < M_ROWS) ra0 = *(const float4*)&A[(size_t)agr0 * 1024 + k0n + aK0];
            if (agr1 < M_ROWS) ra1 = *(const float4*)&A[(size_t)agr1 * 1024 + k0n + aK1];
            #pragma unroll
            for (int it = 0; it < 4; it++) {
                int k = bK + it * 4;
                cp16(smem_u32(&Bs[nxt][k][bN]), &Bw[(size_t)(k0n + k) * ldb + col0 + bN]);
            }
            CP_COMMIT();
        }
        #pragma unroll
        for (int kk = 0; kk < 16; kk++) {
            float4 a0 = *(const float4*)&As[cur][kk][ty * 8];
            float4 a1 = *(const float4*)&As[cur][kk][ty * 8 + 4];
            const ull* bu = (const ull*)&Bs[cur][kk][tx * 8];
            ull b0 = bu[0], b1 = bu[1], b2v = bu[2], b3 = bu[3];
            float av[8] = {a0.x, a0.y, a0.z, a0.w, a1.x, a1.y, a1.z, a1.w};
            #pragma unroll
            for (int i = 0; i < 8; i++) {
                ull ad = pack2(av[i], av[i]);
                fma2(c2[i][0], ad, b0);
                fma2(c2[i][1], ad, b1);
                fma2(c2[i][2], ad, b2v);
                fma2(c2[i][3], ad, b3);
            }
        }
        if (kt < 63) {
            As[nxt][aK0 + 0][aM0] = ra0.x; As[nxt][aK0 + 1][aM0] = ra0.y;
            As[nxt][aK0 + 2][aM0] = ra0.z; As[nxt][aK0 + 3][aM0] = ra0.w;
            As[nxt][aK1 + 0][aM1] = ra1.x; As[nxt][aK1 + 1][aM1] = ra1.y;
            As[nxt][aK1 + 2][aM1] = ra1.z; As[nxt][aK1 + 3][aM1] = ra1.w;
            CP_WAIT0();
            __syncthreads();
        }
    }
    #pragma unroll
    for (int i = 0; i < 8; i++) {
        int gr = row0 + ty * 8 + i;
        if (gr >= M_ROWS) continue;
        #pragma unroll
        for (int j = 0; j < 4; j++) {
            float2 cc = unpack2(c2[i][j]);
            int col = col0 + tx * 8 + j * 2;
            if (Res) {
                float2 r = *(const float2*)&Res[(size_t)gr * 1024 + col];
                cc.x += r.x; cc.y += r.y;
            }
            *(float2*)&C[(size_t)gr * ldc + col] = cc;
        }
    }
}

// ---------------- tiled flash attention (R8/R11-measured; descending-q0 order) ----------
// Q/K/V packed in QKV[M][3072] at offsets h*64 / 1024+h*64 / 2048+h*64.
#define ATQ 128
#define ATK 128
#define QS_LD 132
#define VS_LD 68
#define PS_LD 132
#define ATTN_SMEM ((64 * QS_LD + 64 * QS_LD + ATK * VS_LD + ATK * PS_LD) * 4)

__global__ __launch_bounds__(256) void attn_kernel(const float* __restrict__ QKV,
                                                   float* __restrict__ Om) {
    extern __shared__ float sm[];
    float* Qs = sm;                        // [64][QS_LD]  d-major
    float* Ks = Qs + 64 * QS_LD;           // [64][QS_LD]  d-major
    float* Vs = Ks + 64 * QS_LD;           // [128][VS_LD] k-major
    float* Ps = Vs + ATK * VS_LD;          // [128][PS_LD] k-major, q-cols XOR-swizzled

    const int h = blockIdx.y;
    const int b = blockIdx.z;
    // descending-q0: longest CTAs (most k-tiles) scheduled first
    int q0 = (int)(gridDim.x - 1 - blockIdx.x) * ATQ;
    if (q0 + ATQ > N_CTX) q0 = N_CTX - ATQ;     // overlap recomputes identical rows
    const int tid = threadIdx.x;
    const int tx = tid & 15;
    const int ty = tid >> 4;
    const size_t brow = (size_t)b * N_CTX;
    const float* Qg = QKV + h * 64;
    const float* Kg = QKV + 1024 + h * 64;
    const float* Vg = QKV + 2048 + h * 64;

    // load Q tile transposed, pre-scaled by 1/8
    #pragma unroll
    for (int i = 0; i < 8; i++) {
        int idx = tid + i * 256;           // 0..2047
        int q = idx >> 4;
        int d4 = (idx & 15) << 2;
        float4 v = *(const float4*)(Qg + (brow + q0 + q) * QKV_N + d4);
        Qs[(d4 + 0) * QS_LD + q] = v.x * 0.125f;
        Qs[(d4 + 1) * QS_LD + q] = v.y * 0.125f;
        Qs[(d4 + 2) * QS_LD + q] = v.z * 0.125f;
        Qs[(d4 + 3) * QS_LD + q] = v.w * 0.125f;
    }

    ull o2[8][2];
    #pragma unroll
    for (int i = 0; i < 8; i++) { o2[i][0] = 0ULL; o2[i][1] = 0ULL; }
    float m[8], l[8];
    #pragma unroll
    for (int i = 0; i < 8; i++) { m[i] = -1e30f; l[i] = 0.f; }

    const int ntiles = (q0 + ATQ + ATK - 1) / ATK;
    for (int t = 0; t < ntiles; t++) {
        const int k0 = t * ATK;
        __syncthreads();                   // Ks/Vs free (prev tile done), Qs visible (t=0)
        // load K (transposed) and V for this k-tile
        #pragma unroll
        for (int i = 0; i < 8; i++) {
            int idx = tid + i * 256;
            int k = idx >> 4;
            int d4 = (idx & 15) << 2;
            int kg = k0 + k; if (kg > N_CTX - 1) kg = N_CTX - 1;
            float4 kv = *(const float4*)(Kg + (brow + kg) * QKV_N + d4);
            Ks[(d4 + 0) * QS_LD + k] = kv.x;
            Ks[(d4 + 1) * QS_LD + k] = kv.y;
            Ks[(d4 + 2) * QS_LD + k] = kv.z;
            Ks[(d4 + 3) * QS_LD + k] = kv.w;
            float4 vv = *(const float4*)(Vg + (brow + kg) * QKV_N + d4);
            *(float4*)&Vs[k * VS_LD + d4] = vv;
        }
        __syncthreads();

        // ---- S = Q @ K^T (8x8 micro, FFMA2) ----
        ull c2[8][4];
        #pragma unroll
        for (int i = 0; i < 8; i++)
            #pragma unroll
            for (int j = 0; j < 4; j++) c2[i][j] = 0ULL;
        #pragma unroll 2
        for (int d = 0; d < 64; d++) {
            float4 qa = *(const float4*)&Qs[d * QS_LD + ty * 8];
            float4 qb = *(const float4*)&Qs[d * QS_LD + ty * 8 + 4];
            ulonglong2 k01 = *(const ulonglong2*)&Ks[d * QS_LD + tx * 8];
            ulonglong2 k23 = *(const ulonglong2*)&Ks[d * QS_LD + tx * 8 + 4];
            float qv[8] = {qa.x, qa.y, qa.z, qa.w, qb.x, qb.y, qb.z, qb.w};
            #pragma unroll
            for (int i = 0; i < 8; i++) {
                ull qd = pack2(qv[i], qv[i]);
                fma2(c2[i][0], qd, k01.x);
                fma2(c2[i][1], qd, k01.y);
                fma2(c2[i][2], qd, k23.x);
                fma2(c2[i][3], qd, k23.y);
            }
        }

        // ---- softmax (online, per-row across 16 row-mates) ----
        float s[8][8];
        #pragma unroll
        for (int i = 0; i < 8; i++)
            #pragma unroll
            for (int jp = 0; jp < 4; jp++) {
                float2 u = unpack2(c2[i][jp]);
                s[i][2 * jp] = u.x; s[i][2 * jp + 1] = u.y;
            }
        if (k0 + ATK - 1 > q0) {           // tile touches/crosses diagonal -> mask
            #pragma unroll
            for (int i = 0; i < 8; i++) {
                int qg = q0 + ty * 8 + i;
                #pragma unroll
                for (int j = 0; j < 8; j++)
                    if (k0 + tx * 8 + j > qg) s[i][j] = -1e30f;
            }
        }
        #pragma unroll
        for (int i = 0; i < 8; i++) {
            float mt = s[i][0];
            #pragma unroll
            for (int j = 1; j < 8; j++) mt = fmaxf(mt, s[i][j]);
            mt = fmaxf(mt, __shfl_xor_sync(0xffffffffu, mt, 1));
            mt = fmaxf(mt, __shfl_xor_sync(0xffffffffu, mt, 2));
            mt = fmaxf(mt, __shfl_xor_sync(0xffffffffu, mt, 4));
            mt = fmaxf(mt, __shfl_xor_sync(0xffffffffu, mt, 8));
            float mn = fmaxf(m[i], mt);
            float corr = __expf(m[i] - mn);
            m[i] = mn;
            l[i] *= corr;
            ull cp = pack2(corr, corr);
            o2[i][0] = mul2(o2[i][0], cp);
            o2[i][1] = mul2(o2[i][1], cp);
            float rs = 0.f;
            #pragma unroll
            for (int j = 0; j < 8; j++) {
                float p = __expf(s[i][j] - mn);
                s[i][j] = p;
                rs += p;
            }
            l[i] += rs;
        }

        // ---- store P transposed: Ps[k][q] (swizzled float4 along q) ----
        {
            int swz = 4 * (tx & 7);
            #pragma unroll
            for (int j = 0; j < 8; j++) {
                float* prow = &Ps[(tx * 8 + j) * PS_LD];
                *(float4*)&prow[(ty * 8) ^ swz] =
                    make_float4(s[0][j], s[1][j], s[2][j], s[3][j]);
                *(float4*)&prow[(ty * 8 + 4) ^ swz] =
                    make_float4(s[4][j], s[5][j], s[6][j], s[7][j]);
            }
        }
        __syncthreads();

        // ---- O += P @ V (8q x 4d micro, FFMA2) ----
        #pragma unroll 2
        for (int k = 0; k < ATK; k++) {
            int swz = 4 * ((k >> 3) & 7);
            const float* prow = &Ps[k * PS_LD];
            float4 pa = *(const float4*)&prow[(ty * 8) ^ swz];
            float4 pb = *(const float4*)&prow[(ty * 8 + 4) ^ swz];
            ulonglong2 vv = *(const ulonglong2*)&Vs[k * VS_LD + tx * 4];
            float pv[8] = {pa.x, pa.y, pa.z, pa.w, pb.x, pb.y, pb.z, pb.w};
            #pragma unroll
            for (int i = 0; i < 8; i++) {
                ull pd = pack2(pv[i], pv[i]);
                fma2(o2[i][0], pd, vv.x);
                fma2(o2[i][1], pd, vv.y);
            }
        }
    }

    // ---- finalize: reduce l across row-mates, scale, write ----
    #pragma unroll
    for (int i = 0; i < 8; i++) {
        float lt = l[i];
        lt += __shfl_xor_sync(0xffffffffu, lt, 1);
        lt += __shfl_xor_sync(0xffffffffu, lt, 2);
        lt += __shfl_xor_sync(0xffffffffu, lt, 4);
        lt += __shfl_xor_sync(0xffffffffu, lt, 8);
        float inv = 1.f / lt;
        ull ip = pack2(inv, inv);
        float2 d01 = unpack2(mul2(o2[i][0], ip));
        float2 d23 = unpack2(mul2(o2[i][1], ip));
        float4 w = make_float4(d01.x, d01.y, d23.x, d23.y);
        *(float4*)(Om + (brow + q0 + ty * 8 + i) * D_MODEL + h * 64 + tx * 4) = w;
    }
}

// ---------------- fused logits + softmax into d_out slice l (f32x2 GEMV) ----------------
__global__ __launch_bounds__(256) void probs_kernel(const float* __restrict__ X,
                                                    const float* __restrict__ Wout,
                                                    float* __restrict__ out,
                                                    int l) {
    // rows stored pair-interleaved: xs2[p][k] = (X[row0+2p][k], X[row0+2p+1][k])
    __shared__ ull xs2[4][1024];            // 32 KB
    __shared__ float red[8][8];
    const int tid = threadIdx.x;
    const int row0 = blockIdx.x * 8;

    #pragma unroll
    for (int it = 0; it < 8; it++) {
        int idx = tid + it * 256;           // 0..2047 float4 loads
        int m = idx >> 8;                   // 0..7
        int c4 = idx & 255;
        int gr = row0 + m;
        float4 v = make_float4(0.f, 0.f, 0.f, 0.f);
        if (gr < M_ROWS) v = ((const float4*)&X[(size_t)gr * 1024])[c4];
        float* dst = (float*)&xs2[m >> 1][0];
        int e = m & 1;
        dst[(c4 * 4 + 0) * 2 + e] = v.x;
        dst[(c4 * 4 + 1) * 2 + e] = v.y;
        dst[(c4 * 4 + 2) * 2 + e] = v.z;
        dst[(c4 * 4 + 3) * 2 + e] = v.w;
    }
    __syncthreads();

    ull acce[4], acco[4];
    #pragma unroll
    for (int p = 0; p < 4; p++) { acce[p] = 0ULL; acco[p] = 0ULL; }
    const int v = tid;
    #pragma unroll 2
    for (int k = 0; k < 1024; k += 2) {
        float w0 = Wout[k * VOCAB + v];
        float w1 = Wout[(k + 1) * VOCAB + v];
        ull wp0 = pack2(w0, w0);
        ull wp1 = pack2(w1, w1);
        #pragma unroll
        for (int p = 0; p < 4; p++) {
            ulonglong2 x = *(const ulonglong2*)&xs2[p][k];
            fma2(acce[p], x.x, wp0);
            fma2(acco[p], x.y, wp1);
        }
    }
    float acc[8];
    #pragma unroll
    for (int p = 0; p < 4; p++) {
        float2 e = unpack2(acce[p]);
        float2 o = unpack2(acco[p]);
        acc[2 * p] = e.x + o.x;
        acc[2 * p + 1] = e.y + o.y;
    }

    const int lane = tid & 31;
    const int wid  = tid >> 5;
    float bmax[8];
    #pragma unroll
    for (int m = 0; m < 8; m++) {
        float x = acc[m];
        #pragma unroll
        for (int off = 16; off; off >>= 1)
            x = fmaxf(x, __shfl_xor_sync(0xffffffffu, x, off));
        if (lane == 0) red[m][wid] = x;
    }
    __syncthreads();
    #pragma unroll
    for (int m = 0; m < 8; m++) {
        float mx = red[m][0];
        #pragma unroll
        for (int w = 1; w < 8; w++) mx = fmaxf(mx, red[m][w]);
        bmax[m] = mx;
    }
    __syncthreads();
    float p[8];
    #pragma unroll
    for (int m = 0; m < 8; m++) {
        p[m] = __expf(acc[m] - bmax[m]);
        float x = p[m];
        #pragma unroll
        for (int off = 16; off; off >>= 1)
            x += __shfl_xor_sync(0xffffffffu, x, off);
        if (lane == 0) red[m][wid] = x;
    }
    __syncthreads();
    #pragma unroll
    for (int m = 0; m < 8; m++) {
        float sm = 0.f;
        #pragma unroll
        for (int w = 0; w < 8; w++) sm += red[m][w];
        int gr = row0 + m;
        if (gr < M_ROWS) {
            int b = gr / N_CTX;
            int t = gr - b * N_CTX;
            out[(((size_t)l * B_SZ + b) * N_CTX + t) * VOCAB + v] = p[m] / sm;
        }
    }
}

// ---------------- orchestration ----------------
extern "C" void kernel_launch(void* const* d_in, const int* in_sizes, int n_in,
                              void* d_out, int out_size) {
    const int*   ids  = (const int*)d_in[0];
    const float* emb  = (const float*)d_in[1];
    const float* Wq   = (const float*)d_in[2];
    const float* Wk   = (const float*)d_in[3];
    const float* Wv   = (const float*)d_in[4];
    const float* Wo   = (const float*)d_in[5];
    const float* Wout = (const float*)d_in[6];
    float* out = (float*)d_out;

    float *X, *QKV, *O, *Wc;
    cudaGetSymbolAddress((void**)&X, g_X);
    cudaGetSymbolAddress((void**)&QKV, g_QKV);
    cudaGetSymbolAddress((void**)&O, g_O);
    cudaGetSymbolAddress((void**)&Wc, g_Wc);

    cudaFuncSetAttribute(attn_kernel, cudaFuncAttributeMaxDynamicSharedMemorySize, ATTN_SMEM);

    wconcat_kernel<<<(N_LAYERS * D_MODEL * QKV_N + 255) / 256, 256>>>(Wq, Wk, Wv);
    embed_kernel<<<(M_ROWS * D_MODEL + 255) / 256, 256>>>(ids, emb);
    probs_kernel<<<(M_ROWS + 7) / 8, 256>>>(X, Wout, out, 0);

    dim3 qkvgrid(QKV_N / 128, (M_ROWS + 63) / 64);
    dim3 ogrid(D_MODEL / 128, (M_ROWS + 63) / 64);
    dim3 agrid((N_CTX + ATQ - 1) / ATQ, N_HEADS, B_SZ);
    for (int l = 0; l < N_LAYERS; l++) {
        const float* wc = Wc + (size_t)l * D_MODEL * QKV_N;
        const float* wo = Wo + (size_t)l * D_MODEL * D_MODEL;
        sgemm1024<<<qkvgrid, 128>>>(X, wc, QKV_N, nullptr, QKV, QKV_N);
        attn_kernel<<<agrid, 256, ATTN_SMEM>>>(QKV, O);
        sgemm1024<<<ogrid, 128>>>(O, wo, D_MODEL, X, X, D_MODEL);   // X += O @ Wo
        probs_kernel<<<(M_ROWS + 7) / 8, 256>>>(X, Wout, out, l + 1);
    }
}